// round 11
// baseline (speedup 1.0000x reference)
#include <cuda_runtime.h>
#include <math.h>

#define LSEQ 512
#define BATCH 2
#define DG 256
#define DB 128
#define NH 8
#define HD 32
#define BH (BATCH*NH)   // 16

// ---------------- scratch (device globals; no allocation allowed) ----------------
__device__ float g_xn[BATCH*LSEQ*DG];        // LN(x)                [1024][256]
__device__ float g_q[BH*LSEQ*HD];            // [b*h][l][32]
__device__ float g_k[BH*LSEQ*HD];            // pre-scaled by 1/sqrt(32)
__device__ float g_v[BH*LSEQ*HD];
__device__ float g_gate[BATCH*LSEQ*DG];      // sigmoid(xn@Wg+bg)    [1024][256]
__device__ float g_pb[(size_t)BH*LSEQ*LSEQ]; // pair bias            [b*h][q][k]
__device__ float g_hid[BATCH*LSEQ*DG];       // gate * attn_out      [1024][256]
__device__ float g_wgt[NH*DB];               // b_gamma[i]*Wb[i][h]  [h][i]
__device__ float g_cw[NH];                   // sum_i b_gamma[i]*Wb[i][h]
__device__ float g_bb[NH];                   // b_beta @ Wb[:,h]

// packed f32x2 helpers (sm_10x FFMA2 path — PTX only)
__device__ __forceinline__ void ffma2(unsigned long long& acc,
                                      unsigned long long a,
                                      unsigned long long b) {
    asm("fma.rn.f32x2 %0, %1, %2, %0;" : "+l"(acc) : "l"(a), "l"(b));
}
__device__ __forceinline__ void fadd2(unsigned long long& acc, unsigned long long a) {
    asm("add.rn.f32x2 %0, %1, %0;" : "+l"(acc) : "l"(a));
}
__device__ __forceinline__ float2 unpack2(unsigned long long v) {
    float2 r;
    asm("mov.b64 {%0, %1}, %2;" : "=f"(r.x), "=f"(r.y) : "l"(v));
    return r;
}

// ============ merged kernel 1: prep_wb (block 0) + ln_x (blocks 1..128) ============
__global__ void __launch_bounds__(256) prep_and_lnx(
        const float* __restrict__ b_gamma, const float* __restrict__ b_beta,
        const float* __restrict__ Wb,
        const float* __restrict__ x, const float* __restrict__ gamma,
        const float* __restrict__ beta) {
    int tid = threadIdx.x;
    if (blockIdx.x == 0) {
        // ---- prep_wb (128 threads) ----
        __shared__ float sc[NH][DB];
        __shared__ float sb[NH][DB];
        if (tid < DB) {
            float g = b_gamma[tid];
            float bt = b_beta[tid];
#pragma unroll
            for (int h = 0; h < NH; h++) {
                float w = Wb[tid*NH + h];
                g_wgt[h*DB + tid] = g * w;
                sc[h][tid] = g * w;
                sb[h][tid] = bt * w;
            }
        }
        __syncthreads();
        if (tid < NH) {
            float a = 0.f, b2 = 0.f;
            for (int j = 0; j < DB; j++) { a += sc[tid][j]; b2 += sb[tid][j]; }
            g_cw[tid] = a;
            g_bb[tid] = b2;
        }
        return;
    }
    // ---- ln_x: 8 warps -> 8 rows per block ----
    int warp = tid >> 5, lane = tid & 31;
    int row = (blockIdx.x - 1) * 8 + warp;     // 1024 rows over 128 blocks
    const float* rp = x + (size_t)row * DG;
    float4 v0 = *(const float4*)(rp + lane*4);
    float4 v1 = *(const float4*)(rp + 128 + lane*4);
    float s1 = v0.x+v0.y+v0.z+v0.w + v1.x+v1.y+v1.z+v1.w;
    float s2 = v0.x*v0.x+v0.y*v0.y+v0.z*v0.z+v0.w*v0.w
             + v1.x*v1.x+v1.y*v1.y+v1.z*v1.z+v1.w*v1.w;
#pragma unroll
    for (int off = 16; off; off >>= 1) {
        s1 += __shfl_xor_sync(0xffffffffu, s1, off);
        s2 += __shfl_xor_sync(0xffffffffu, s2, off);
    }
    float mu = s1 * (1.f/256.f);
    float var = s2 * (1.f/256.f) - mu*mu;
    float rstd = rsqrtf(var + 1e-5f);
    float4 gm0 = *(const float4*)(gamma + lane*4);
    float4 gm1 = *(const float4*)(gamma + 128 + lane*4);
    float4 bt0 = *(const float4*)(beta + lane*4);
    float4 bt1 = *(const float4*)(beta + 128 + lane*4);
    float4 o0, o1;
    o0.x = (v0.x-mu)*rstd*gm0.x + bt0.x; o0.y = (v0.y-mu)*rstd*gm0.y + bt0.y;
    o0.z = (v0.z-mu)*rstd*gm0.z + bt0.z; o0.w = (v0.w-mu)*rstd*gm0.w + bt0.w;
    o1.x = (v1.x-mu)*rstd*gm1.x + bt1.x; o1.y = (v1.y-mu)*rstd*gm1.y + bt1.y;
    o1.z = (v1.z-mu)*rstd*gm1.z + bt1.z; o1.w = (v1.w-mu)*rstd*gm1.w + bt1.w;
    *(float4*)(g_xn + (size_t)row*DG + lane*4) = o0;
    *(float4*)(g_xn + (size_t)row*DG + 128 + lane*4) = o1;
}

// ============ merged kernel 2: gemm_qkvg (blocks 0..255) + pair_ln (256..8447) ====
// gemm blocks first in grid order -> wave-1 schedules them alongside pair_ln
// blocks; the compute-bound gemm hides inside pair_ln's DRAM stalls.
__global__ void __launch_bounds__(256, 4) fused_qkvg_pairln(
        const float* __restrict__ Wq, const float* __restrict__ Wk,
        const float* __restrict__ Wv, const float* __restrict__ Wg,
        const float* __restrict__ bg, const float* __restrict__ bias) {
    __shared__ __align__(16) float smem[2*16*68];   // union for both branches
    int tid = threadIdx.x;

    if (blockIdx.x < 256) {
        // ---------------- gemm_qkvg ----------------
        float* Ast = smem;            // [k][m] transposed, padded 68
        float* Bs  = smem + 16*68;    // [k][n], padded 68
        int id = blockIdx.x;
        int bm = (id >> 4) * 64;
        int bn_g = (id & 15) * 64;           // 0..1023
        int which = bn_g >> 8;               // 0:Q 1:K 2:V 3:G
        int bn = bn_g & 255;
        const float* W = (which==0) ? Wq : (which==1) ? Wk : (which==2) ? Wv : Wg;
        int ty = tid >> 4, tx = tid & 15;
        int ar = tid >> 2, ac4 = tid & 3;
        int br = tid >> 4, bc4 = tid & 15;
        float acc[4][4] = {};
        for (int kb = 0; kb < 256; kb += 16) {
            float4 av = *(const float4*)(g_xn + (size_t)(bm+ar)*256 + kb + ac4*4);
            Ast[(ac4*4+0)*68 + ar] = av.x;
            Ast[(ac4*4+1)*68 + ar] = av.y;
            Ast[(ac4*4+2)*68 + ar] = av.z;
            Ast[(ac4*4+3)*68 + ar] = av.w;
            *(float4*)&Bs[br*68 + bc4*4] = *(const float4*)(W + (size_t)(kb+br)*256 + bn + bc4*4);
            __syncthreads();
#pragma unroll
            for (int k = 0; k < 16; k++) {
                float4 a = *(float4*)&Ast[k*68 + ty*4];
                float4 b = *(float4*)&Bs [k*68 + tx*4];
                acc[0][0]=fmaf(a.x,b.x,acc[0][0]); acc[0][1]=fmaf(a.x,b.y,acc[0][1]);
                acc[0][2]=fmaf(a.x,b.z,acc[0][2]); acc[0][3]=fmaf(a.x,b.w,acc[0][3]);
                acc[1][0]=fmaf(a.y,b.x,acc[1][0]); acc[1][1]=fmaf(a.y,b.y,acc[1][1]);
                acc[1][2]=fmaf(a.y,b.z,acc[1][2]); acc[1][3]=fmaf(a.y,b.w,acc[1][3]);
                acc[2][0]=fmaf(a.z,b.x,acc[2][0]); acc[2][1]=fmaf(a.z,b.y,acc[2][1]);
                acc[2][2]=fmaf(a.z,b.z,acc[2][2]); acc[2][3]=fmaf(a.z,b.w,acc[2][3]);
                acc[3][0]=fmaf(a.w,b.x,acc[3][0]); acc[3][1]=fmaf(a.w,b.y,acc[3][1]);
                acc[3][2]=fmaf(a.w,b.z,acc[3][2]); acc[3][3]=fmaf(a.w,b.w,acc[3][3]);
            }
            __syncthreads();
        }
        const float kscale = 0.17677669529663687f; // 1/sqrt(32)
#pragma unroll
        for (int i = 0; i < 4; i++) {
#pragma unroll
            for (int j = 0; j < 4; j++) {
                int m = bm + ty*4 + i;
                int n = bn + tx*4 + j;
                float v = acc[i][j];
                if (which < 3) {
                    if (which == 1) v *= kscale;
                    int b = m >> 9, pos = m & 511, h = n >> 5, d = n & 31;
                    float* dst = (which==0) ? g_q : (which==1) ? g_k : g_v;
                    dst[((size_t)(b*NH + h)*LSEQ + pos)*HD + d] = v;
                } else {
                    v = 1.f / (1.f + __expf(-(v + bg[n])));
                    g_gate[(size_t)m*DG + n] = v;
                }
            }
        }
        return;
    }

    // ---------------- pair_ln ----------------
    // Warp = 8 rows (sub -> rows base+sub, base+sub+4), lane li owns contiguous
    // 16B chunks. Eager head-pair reduction keeps regs <= 64.
    float* swg = smem;                        // NH*DB = 1024 floats
    float* scw = smem + NH*DB;                // 8
    float* sbb = smem + NH*DB + NH;           // 8
    float* sval = smem + NH*DB + 2*NH;        // 8*72 = 576
    unsigned pbid = blockIdx.x - 256u;
    for (int i = tid; i < NH*DB; i += 256) swg[i] = g_wgt[i];
    if (tid < NH) { scw[tid] = g_cw[tid]; sbb[tid] = g_bb[tid]; }
    __syncthreads();
    int warp = tid >> 5, lane = tid & 31;
    int sub = lane >> 3, li = lane & 7;
    int b0 = li & 1;
    unsigned rowA = pbid * 64u + warp * 8u + sub;   // < 524288
    const ulonglong2* rpA = (const ulonglong2*)(bias + (size_t)rowA * DB);
    const ulonglong2* rpB = (const ulonglong2*)(bias + (size_t)(rowA + 4u) * DB);

    unsigned long long xa[8], xb[8];
#pragma unroll
    for (int j = 0; j < 4; j++) {
        ulonglong2 t = rpA[j*8 + li];
        xa[2*j] = t.x; xa[2*j+1] = t.y;
    }
#pragma unroll
    for (int j = 0; j < 4; j++) {
        ulonglong2 t = rpB[j*8 + li];
        xb[2*j] = t.x; xb[2*j+1] = t.y;
    }

    unsigned long long s1a = xa[0], s2a = 0ull;
    unsigned long long s1b = xb[0], s2b = 0ull;
    ffma2(s2a, xa[0], xa[0]);
    ffma2(s2b, xb[0], xb[0]);
#pragma unroll
    for (int j = 1; j < 8; j++) {
        fadd2(s1a, xa[j]); ffma2(s2a, xa[j], xa[j]);
        fadd2(s1b, xb[j]); ffma2(s2b, xb[j], xb[j]);
    }
    float2 t;
    t = unpack2(s1a); float sa1 = t.x + t.y;
    t = unpack2(s2a); float sa2 = t.x + t.y;
    t = unpack2(s1b); float sb1 = t.x + t.y;
    t = unpack2(s2b); float sb2 = t.x + t.y;
#pragma unroll
    for (int off = 4; off; off >>= 1) {
        sa1 += __shfl_xor_sync(0xffffffffu, sa1, off);
        sa2 += __shfl_xor_sync(0xffffffffu, sa2, off);
        sb1 += __shfl_xor_sync(0xffffffffu, sb1, off);
        sb2 += __shfl_xor_sync(0xffffffffu, sb2, off);
    }
    float muA = sa1 * (1.f/128.f);
    float rsA = rsqrtf(fmaf(sa2, 1.f/128.f, -muA*muA) + 1e-5f);
    float muB = sb1 * (1.f/128.f);
    float rsB = rsqrtf(fmaf(sb2, 1.f/128.f, -muB*muB) + 1e-5f);

    const ulonglong2* wsp = (const ulonglong2*)swg;  // index: h*32 + j*8 + li
    float dhA = 0.f, dhB = 0.f;
#pragma unroll
    for (int p = 0; p < 4; p++) {
        unsigned long long aA0 = 0ull, aA1 = 0ull, aB0 = 0ull, aB1 = 0ull;
#pragma unroll
        for (int j = 0; j < 4; j++) {
            ulonglong2 w0 = wsp[(2*p  )*32 + j*8 + li];
            ulonglong2 w1 = wsp[(2*p+1)*32 + j*8 + li];
            ffma2(aA0, xa[2*j],   w0.x); ffma2(aA0, xa[2*j+1], w0.y);
            ffma2(aA1, xa[2*j],   w1.x); ffma2(aA1, xa[2*j+1], w1.y);
            ffma2(aB0, xb[2*j],   w0.x); ffma2(aB0, xb[2*j+1], w0.y);
            ffma2(aB1, xb[2*j],   w1.x); ffma2(aB1, xb[2*j+1], w1.y);
        }
        float2 u;
        u = unpack2(aA0); float fA0 = u.x + u.y;
        u = unpack2(aA1); float fA1 = u.x + u.y;
        u = unpack2(aB0); float fB0 = u.x + u.y;
        u = unpack2(aB1); float fB1 = u.x + u.y;
        float sA = b0 ? fA0 : fA1;
        float rA = (b0 ? fA1 : fA0) + __shfl_xor_sync(0xffffffffu, sA, 1);
        rA += __shfl_xor_sync(0xffffffffu, rA, 2);
        rA += __shfl_xor_sync(0xffffffffu, rA, 4);
        float sB = b0 ? fB0 : fB1;
        float rB = (b0 ? fB1 : fB0) + __shfl_xor_sync(0xffffffffu, sB, 1);
        rB += __shfl_xor_sync(0xffffffffu, rB, 2);
        rB += __shfl_xor_sync(0xffffffffu, rB, 4);
        if ((li >> 1) == p) { dhA = rA; dhB = rB; }
    }

    float valA = fmaf(rsA, dhA - muA*scw[li], sbb[li]);
    float valB = fmaf(rsB, dhB - muB*scw[li], sbb[li]);

    sval[warp*72 + li*9 + sub]     = valA;
    sval[warp*72 + li*9 + sub + 4] = valB;
    __syncthreads();

    unsigned rblk = pbid * 64u;
    unsigned bq = rblk >> 18;
    unsigned q  = (rblk >> 9) & 511u;
    unsigned k0 = rblk & 511u;
    int h  = tid >> 5;
    int kk = tid & 31;
    float* outp = g_pb + ((size_t)(bq*NH + h)*LSEQ + q)*LSEQ + k0;
    outp[kk]      = sval[(kk >> 3)*72      + h*9 + (kk & 7)];
    outp[kk + 32] = sval[((kk+32) >> 3)*72 + h*9 + (kk & 7)];
}

// ---------------- flash-style attention + gate (R4 config: 16 q rows, 512 blocks)
__global__ void __launch_bounds__(128) attn_kernel() {
    __shared__ __align__(16) float Qs[16*36];
    __shared__ __align__(16) float Ks[64*36];
    __shared__ __align__(16) float Vs[64*32];
    __shared__ __align__(16) float Ps[16*68];
    int tid = threadIdx.x;
    int bh = blockIdx.x >> 5;              // 512 blocks = 16 bh * 32 q-tiles
    int q0 = (blockIdx.x & 31) * 16;
    const float* Qg = g_q + (size_t)bh * LSEQ * HD;
    const float* Kg = g_k + (size_t)bh * LSEQ * HD;
    const float* Vg = g_v + (size_t)bh * LSEQ * HD;
    {
        int r = tid >> 3, c = tid & 7;
        *(float4*)&Qs[r*36 + c*4] = *(const float4*)(Qg + (size_t)(q0+r)*HD + c*4);
    }
    int ty = tid >> 3, tx = tid & 7;
    const float* pb = g_pb + ((size_t)bh * LSEQ + q0 + ty) * LSEQ;
    float m = __int_as_float(0xff800000u);
    float lsum = 0.f;
    float acc[4] = {0,0,0,0};

    for (int kt = 0; kt < LSEQ; kt += 64) {
        __syncthreads();
        for (int i = tid; i < 512; i += 128) {
            int r = i >> 3, c = i & 7;
            *(float4*)&Ks[r*36 + c*4] = *(const float4*)(Kg + (size_t)(kt+r)*HD + c*4);
        }
        for (int i = tid; i < 512; i += 128) {
            int r = i >> 3, c = i & 7;
            *(float4*)&Vs[r*32 + c*4] = *(const float4*)(Vg + (size_t)(kt+r)*HD + c*4);
        }
        __syncthreads();
        float sv[8];
#pragma unroll
        for (int j = 0; j < 8; j++) sv[j] = pb[kt + tx + 8*j];
#pragma unroll
        for (int d4 = 0; d4 < 8; d4++) {
            float4 a = *(float4*)&Qs[ty*36 + d4*4];
#pragma unroll
            for (int j = 0; j < 8; j++) {
                float4 kv = *(float4*)&Ks[(tx + 8*j)*36 + d4*4];
                sv[j] = fmaf(a.x,kv.x, fmaf(a.y,kv.y, fmaf(a.z,kv.z, fmaf(a.w,kv.w, sv[j]))));
            }
        }
        float mx = sv[0];
#pragma unroll
        for (int j = 1; j < 8; j++) mx = fmaxf(mx, sv[j]);
#pragma unroll
        for (int off = 4; off; off >>= 1)
            mx = fmaxf(mx, __shfl_xor_sync(0xffffffffu, mx, off));
        float mn = fmaxf(m, mx);
        float sc = __expf(m - mn);
        float sum = 0.f;
#pragma unroll
        for (int j = 0; j < 8; j++) { sv[j] = __expf(sv[j] - mn); sum += sv[j]; }
#pragma unroll
        for (int off = 4; off; off >>= 1)
            sum += __shfl_xor_sync(0xffffffffu, sum, off);
        lsum = lsum*sc + sum;
        m = mn;
#pragma unroll
        for (int j = 0; j < 4; j++) acc[j] *= sc;
#pragma unroll
        for (int j = 0; j < 8; j++) Ps[ty*68 + tx + 8*j] = sv[j];
        __syncthreads();
#pragma unroll
        for (int k4 = 0; k4 < 16; k4++) {
            float4 pa = *(float4*)&Ps[ty*68 + k4*4];
            float4 va = *(float4*)&Vs[(k4*4+0)*32 + tx*4];
            float4 vb = *(float4*)&Vs[(k4*4+1)*32 + tx*4];
            float4 vc = *(float4*)&Vs[(k4*4+2)*32 + tx*4];
            float4 vd = *(float4*)&Vs[(k4*4+3)*32 + tx*4];
            acc[0]=fmaf(pa.x,va.x,acc[0]); acc[1]=fmaf(pa.x,va.y,acc[1]); acc[2]=fmaf(pa.x,va.z,acc[2]); acc[3]=fmaf(pa.x,va.w,acc[3]);
            acc[0]=fmaf(pa.y,vb.x,acc[0]); acc[1]=fmaf(pa.y,vb.y,acc[1]); acc[2]=fmaf(pa.y,vb.z,acc[2]); acc[3]=fmaf(pa.y,vb.w,acc[3]);
            acc[0]=fmaf(pa.z,vc.x,acc[0]); acc[1]=fmaf(pa.z,vc.y,acc[1]); acc[2]=fmaf(pa.z,vc.z,acc[2]); acc[3]=fmaf(pa.z,vc.w,acc[3]);
            acc[0]=fmaf(pa.w,vd.x,acc[0]); acc[1]=fmaf(pa.w,vd.y,acc[1]); acc[2]=fmaf(pa.w,vd.z,acc[2]); acc[3]=fmaf(pa.w,vd.w,acc[3]);
        }
    }
    float inv = 1.f / lsum;
    int b = bh >> 3, h = bh & 7;
    int mrow = b * LSEQ + q0 + ty;
    float4 g = *(const float4*)(g_gate + (size_t)mrow * DG + h*HD + tx*4);
    float4 o = make_float4(acc[0]*inv*g.x, acc[1]*inv*g.y, acc[2]*inv*g.z, acc[3]*inv*g.w);
    *(float4*)(g_hid + (size_t)mrow*DG + h*HD + tx*4) = o;
}

// ---------------- final GEMM: hid @ Wout + bout ----------------
// 16M x 64N tiles -> grid 256 (~1.7 CTA/SM) + REGISTER DOUBLE-BUFFERING:
// prefetch chunk kb+16 into regs right after the sync, compute chunk kb from
// smem -> the ~250cyc L2 load latency overlaps compute instead of serializing
// (R9 was 1 CTA/SM with a bare latency chain: 19us for 134 MFLOP).
__global__ void __launch_bounds__(256) gemm_out(const float* __restrict__ Wout,
                                                const float* __restrict__ bout,
                                                float* __restrict__ out) {
    __shared__ __align__(16) float Ast[16*18];   // [k][m] transposed, pad 18
    __shared__ __align__(16) float Bs [16*68];   // [k][n], pad 68
    int tid = threadIdx.x;
    int bm = blockIdx.y * 16;
    int bn = blockIdx.x * 64;
    int ty = tid >> 4, tx = tid & 15;            // row ty, cols tx*4
    int ar = tid & 15, ac4 = tid >> 4;           // A loaders: tid<64
    int br = tid >> 4, bc4 = tid & 15;
    float acc[4] = {0,0,0,0};

    // prologue: load chunk 0 into registers
    float4 av, bv;
    if (tid < 64) av = *(const float4*)(g_hid + (size_t)(bm+ar)*256 + ac4*4);
    bv = *(const float4*)(Wout + (size_t)br*256 + bn + bc4*4);

    for (int kb = 0; kb < 256; kb += 16) {
        if (tid < 64) {
            Ast[(ac4*4+0)*18 + ar] = av.x;
            Ast[(ac4*4+1)*18 + ar] = av.y;
            Ast[(ac4*4+2)*18 + ar] = av.z;
            Ast[(ac4*4+3)*18 + ar] = av.w;
        }
        *(float4*)&Bs[br*68 + bc4*4] = bv;
        __syncthreads();
        if (kb < 240) {   // prefetch next chunk (overlaps with compute below)
            if (tid < 64) av = *(const float4*)(g_hid + (size_t)(bm+ar)*256 + kb+16 + ac4*4);
            bv = *(const float4*)(Wout + (size_t)(kb+16+br)*256 + bn + bc4*4);
        }
#pragma unroll
        for (int k = 0; k < 16; k++) {
            float a = Ast[k*18 + ty];
            float4 b = *(float4*)&Bs[k*68 + tx*4];
            acc[0]=fmaf(a,b.x,acc[0]); acc[1]=fmaf(a,b.y,acc[1]);
            acc[2]=fmaf(a,b.z,acc[2]); acc[3]=fmaf(a,b.w,acc[3]);
        }
        __syncthreads();
    }
    float4 bo = *(const float4*)(bout + bn + tx*4);
    int m = bm + ty;
    float4 o = make_float4(acc[0] + bo.x, acc[1] + bo.y, acc[2] + bo.z, acc[3] + bo.w);
    *(float4*)(out + (size_t)m*256 + bn + tx*4) = o;
}

// ---------------- launch ----------------
extern "C" void kernel_launch(void* const* d_in, const int* in_sizes, int n_in,
                              void* d_out, int out_size) {
    const float* x       = (const float*)d_in[0];
    const float* bias    = (const float*)d_in[1];
    const float* g_gamma = (const float*)d_in[2];
    const float* g_beta  = (const float*)d_in[3];
    const float* b_gamma = (const float*)d_in[4];
    const float* b_beta  = (const float*)d_in[5];
    const float* Wq      = (const float*)d_in[6];
    const float* Wk      = (const float*)d_in[7];
    const float* Wv      = (const float*)d_in[8];
    const float* Wb      = (const float*)d_in[9];
    const float* Wg      = (const float*)d_in[10];
    const float* bg      = (const float*)d_in[11];
    const float* Wout    = (const float*)d_in[12];
    const float* bout    = (const float*)d_in[13];
    float* out = (float*)d_out;

    prep_and_lnx<<<129, 256>>>(b_gamma, b_beta, Wb, x, g_gamma, g_beta);
    fused_qkvg_pairln<<<8448, 256>>>(Wq, Wk, Wv, Wg, bg, bias);
    attn_kernel<<<512, 128>>>();
    gemm_out<<<dim3(4, 64), 256>>>(Wout, bout, out);
}